// round 3
// baseline (speedup 1.0000x reference)
#include <cuda_runtime.h>
#include <math.h>

// ---------------- problem constants ----------------
#define N_TOT   100000
#define N_SEL   5000        // 5 blocks * 1000
#define NB      5
#define BATCH   1000
#define DIMS    256
#define NBUCK   65536       // 16-bit MSB buckets for stable sort
#define PARTITIONABLE 1

// ---------------- scratch (static device globals; no allocations) ----------------
__device__ unsigned g_key[N_TOT];
__device__ unsigned g_keyB[N_TOT], g_valB[N_TOT], g_idxB[N_TOT];
__device__ unsigned g_keyC[N_TOT], g_valC[N_TOT], g_idxC[N_TOT];
__device__ unsigned g_cnt[NBUCK], g_start[NBUCK], g_cur[NBUCK];
__device__ unsigned g_bsum[64];
__device__ float    g_X[(size_t)N_SEL * DIMS];
__device__ float    g_sq[N_SEL];
__device__ int      g_lab[N_SEL];
__device__ unsigned g_ap[N_SEL], g_an[N_SEL];   // float bits; dist >= 0 so unsigned order == float order

// ---------------- threefry-2x32-20 (exact JAX algorithm) ----------------
__device__ __forceinline__ void tf2x32(unsigned k0, unsigned k1, unsigned x0, unsigned x1,
                                       unsigned &o0, unsigned &o1) {
    unsigned ks2 = k0 ^ k1 ^ 0x1BD11BDAu;
    x0 += k0; x1 += k1;
#define TFR(r) { x0 += x1; x1 = (x1 << (r)) | (x1 >> (32 - (r))); x1 ^= x0; }
    TFR(13) TFR(15) TFR(26) TFR(6)   x0 += k1;  x1 += ks2 + 1u;
    TFR(17) TFR(29) TFR(16) TFR(24)  x0 += ks2; x1 += k0  + 2u;
    TFR(13) TFR(15) TFR(26) TFR(6)   x0 += k0;  x1 += k1  + 3u;
    TFR(17) TFR(29) TFR(16) TFR(24)  x0 += k1;  x1 += ks2 + 4u;
    TFR(13) TFR(15) TFR(26) TFR(6)   x0 += ks2; x1 += k0  + 5u;
#undef TFR
    o0 = x0; o1 = x1;
}

__device__ __forceinline__ void get_subkey(unsigned uu, int round, unsigned &s0, unsigned &s1) {
    unsigned K0 = 0u, K1 = uu;
#if PARTITIONABLE
    for (int j = 0;; j++) {
        tf2x32(K0, K1, 0u, 1u, s0, s1);
        if (j == round) break;
        unsigned n0, n1; tf2x32(K0, K1, 0u, 0u, n0, n1);
        K0 = n0; K1 = n1;
    }
#else
    for (int j = 0;; j++) {
        unsigned a0, a1, b0, b1;
        tf2x32(K0, K1, 0u, 2u, a0, a1);
        tf2x32(K0, K1, 1u, 3u, b0, b1);
        s0 = a1; s1 = b1;
        if (j == round) break;
        K0 = a0; K1 = b0;
    }
#endif
}

// ---------------- kernels ----------------
__global__ void k_init_all() {
    int i = blockIdx.x * blockDim.x + threadIdx.x;
    if (i < NBUCK) g_cnt[i] = 0u;
    if (i < N_SEL) { g_ap[i] = 0u; g_an[i] = 0x7f800000u; }
}

__global__ void k_zero_cnt() {
    int i = blockIdx.x * blockDim.x + threadIdx.x;
    if (i < NBUCK) g_cnt[i] = 0u;
}

// fused: compute threefry keys AND build the 16-bit-MSB histogram in one pass
__global__ void k_keys_hist(const int* uuP, int round) {
    int i = blockIdx.x * blockDim.x + threadIdx.x;
    if (i >= N_TOT) return;
    unsigned uu = (unsigned)uuP[0];
    unsigned s0, s1; get_subkey(uu, round, s0, s1);
    unsigned o0, o1; tf2x32(s0, s1, 0u, (unsigned)i, o0, o1);
    g_key[i] = o0;
    atomicAdd(&g_cnt[o0 >> 16], 1u);
}

// ---- 3-stage grid-wide exclusive scan over 65536 counters ----
// stage A: 64 blocks x 1024 threads; per-block exclusive scan + block total
__global__ void k_scanA() {
    __shared__ unsigned s[1024];
    int t = threadIdx.x;
    int g = blockIdx.x * 1024 + t;
    unsigned v = g_cnt[g];
    s[t] = v;
    __syncthreads();
    for (int off = 1; off < 1024; off <<= 1) {
        unsigned u = (t >= off) ? s[t - off] : 0u;
        __syncthreads();
        s[t] += u;
        __syncthreads();
    }
    g_start[g] = s[t] - v;                // exclusive within block
    if (t == 1023) g_bsum[blockIdx.x] = s[t];
}

// stage B: exclusive scan of the 64 block totals
__global__ void k_scanB() {
    __shared__ unsigned s[64];
    int t = threadIdx.x;
    unsigned v = g_bsum[t];
    s[t] = v;
    __syncthreads();
    for (int off = 1; off < 64; off <<= 1) {
        unsigned u = (t >= off) ? s[t - off] : 0u;
        __syncthreads();
        s[t] += u;
        __syncthreads();
    }
    g_bsum[t] = s[t] - v;
}

// stage C: add block offsets, materialize g_start / g_cur
__global__ void k_scanC() {
    int g = blockIdx.x * 1024 + threadIdx.x;
    unsigned st = g_start[g] + g_bsum[blockIdx.x];
    g_start[g] = st;
    g_cur[g]   = st;
}

__global__ void k_scatter(int round) {
    int i = blockIdx.x * blockDim.x + threadIdx.x;
    if (i >= N_TOT) return;
    unsigned k = g_key[i];
    unsigned p = atomicAdd(&g_cur[k >> 16], 1u);
    if (round == 0) { g_keyB[p] = k; g_valB[p] = (unsigned)i;  g_idxB[p] = (unsigned)i; }
    else            { g_keyC[p] = k; g_valC[p] = g_valB[i];    g_idxC[p] = (unsigned)i; }
}

// restore exact stable order within each bucket: sort by (full key, original index)
__global__ void k_bsort(int round) {
    int b = blockIdx.x * blockDim.x + threadIdx.x;
    if (b >= NBUCK) return;
    unsigned n = g_cnt[b];
    if (n < 2u) return;
    unsigned s = g_start[b];
    unsigned* key = round ? g_keyC : g_keyB;
    unsigned* val = round ? g_valC : g_valB;
    unsigned* idx = round ? g_idxC : g_idxB;
    for (unsigned a = s + 1u; a < s + n; a++) {
        unsigned k = key[a], v = val[a], x = idx[a];
        int c = (int)a - 1;
        while (c >= (int)s && (key[c] > k || (key[c] == k && idx[c] > x))) {
            key[c + 1] = key[c]; val[c + 1] = val[c]; idx[c + 1] = idx[c];
            c--;
        }
        key[c + 1] = k; val[c + 1] = v; idx[c + 1] = x;
    }
}

// gather the first 5000 permuted rows + per-row squared norm + label
__global__ void k_gather(const float* __restrict__ X, const int* __restrict__ T) {
    int row = blockIdx.x;
    int t = threadIdx.x;           // 64 threads, one float4 each
    unsigned src = g_valC[row];
    float4 v = ((const float4*)(X + (size_t)src * DIMS))[t];
    ((float4*)(g_X + (size_t)row * DIMS))[t] = v;
    float ss = v.x * v.x + v.y * v.y + v.z * v.z + v.w * v.w;
    __shared__ float red[64];
    red[t] = ss;
    __syncthreads();
    if (t < 32) {
        float x = red[t] + red[t + 32];
        for (int o = 16; o > 0; o >>= 1) x += __shfl_down_sync(0xffffffffu, x, o);
        if (t == 0) { g_sq[row] = x; g_lab[row] = T[src]; }
    }
}

// fused  G = Xb*Xb^T  +  dist  +  batch-hard mining
__global__ void k_main() {
    extern __shared__ float sm[];
    float* As  = sm;                 // [256][64] k-major
    float* Bs  = sm + 256 * 64;
    float* sqA = sm + 2 * 256 * 64;
    float* sqB = sqA + 64;
    int*   labA = (int*)(sqB + 64);
    int*   labB = labA + 64;

    const int tid = threadIdx.x;
    const int tx = tid & 15, ty = tid >> 4;
    const int blk = blockIdx.z;
    const int r0 = blockIdx.x * 64;
    const int cStart = blockIdx.y * 500;
    const int cEnd = cStart + 500;
    const int nrows = min(64, BATCH - r0);
    const int rowBase = blk * BATCH + r0;

    for (int idx = tid; idx < 64 * 64; idx += 256) {
        int r = idx & 63, q = idx >> 6;
        float4 v = make_float4(0.f, 0.f, 0.f, 0.f);
        if (r < nrows) v = *(const float4*)&g_X[(size_t)(rowBase + r) * DIMS + q * 4];
        As[(q * 4 + 0) * 64 + r] = v.x;
        As[(q * 4 + 1) * 64 + r] = v.y;
        As[(q * 4 + 2) * 64 + r] = v.z;
        As[(q * 4 + 3) * 64 + r] = v.w;
    }
    if (tid < 64) {
        sqA[tid]  = (tid < nrows) ? g_sq[rowBase + tid] : 0.f;
        labA[tid] = (tid < nrows) ? g_lab[rowBase + tid] : -1;
    }

    float rmax[4] = {0.f, 0.f, 0.f, 0.f};
    float rmin[4];
    rmin[0] = rmin[1] = rmin[2] = rmin[3] = __uint_as_float(0x7f800000u);

    for (int c0 = cStart; c0 < cEnd; c0 += 64) {
        const int ncols = min(64, cEnd - c0);
        const int colBase = blk * BATCH + c0;
        __syncthreads();
        for (int idx = tid; idx < 64 * 64; idx += 256) {
            int r = idx & 63, q = idx >> 6;
            float4 v = make_float4(0.f, 0.f, 0.f, 0.f);
            if (r < ncols) v = *(const float4*)&g_X[(size_t)(colBase + r) * DIMS + q * 4];
            Bs[(q * 4 + 0) * 64 + r] = v.x;
            Bs[(q * 4 + 1) * 64 + r] = v.y;
            Bs[(q * 4 + 2) * 64 + r] = v.z;
            Bs[(q * 4 + 3) * 64 + r] = v.w;
        }
        if (tid < 64) {
            sqB[tid]  = (tid < ncols) ? g_sq[colBase + tid] : 0.f;
            labB[tid] = (tid < ncols) ? g_lab[colBase + tid] : 0x7fffffff;
        }
        __syncthreads();

        float acc[4][4];
#pragma unroll
        for (int i = 0; i < 4; i++)
#pragma unroll
            for (int j = 0; j < 4; j++) acc[i][j] = 0.f;

#pragma unroll 8
        for (int k = 0; k < DIMS; k++) {
            float4 a = *(const float4*)&As[k * 64 + ty * 4];
            float4 b = *(const float4*)&Bs[k * 64 + tx * 4];
            acc[0][0] += a.x * b.x; acc[0][1] += a.x * b.y; acc[0][2] += a.x * b.z; acc[0][3] += a.x * b.w;
            acc[1][0] += a.y * b.x; acc[1][1] += a.y * b.y; acc[1][2] += a.y * b.z; acc[1][3] += a.y * b.w;
            acc[2][0] += a.z * b.x; acc[2][1] += a.z * b.y; acc[2][2] += a.z * b.z; acc[2][3] += a.z * b.w;
            acc[3][0] += a.w * b.x; acc[3][1] += a.w * b.y; acc[3][2] += a.w * b.z; acc[3][3] += a.w * b.w;
        }

#pragma unroll
        for (int i = 0; i < 4; i++) {
            int gr = ty * 4 + i;
            float sqi = sqA[gr];
            int   li  = labA[gr];
#pragma unroll
            for (int j = 0; j < 4; j++) {
                int gc = tx * 4 + j;
                if (gr < nrows && gc < ncols) {
                    float d2 = sqi + sqB[gc] - 2.f * acc[i][j];
                    float dist = sqrtf(fmaxf(d2, 1e-12f));
                    if (li == labB[gc]) rmax[i] = fmaxf(rmax[i], dist);
                    else                rmin[i] = fminf(rmin[i], dist);
                }
            }
        }
    }

#pragma unroll
    for (int i = 0; i < 4; i++) {
        int gr = ty * 4 + i;
        if (gr < nrows) {
            int row = rowBase + gr;
            atomicMax(&g_ap[row], __float_as_uint(rmax[i]));
            atomicMin(&g_an[row], __float_as_uint(rmin[i]));
        }
    }
}

__global__ void k_reduce(float* __restrict__ out) {
    __shared__ float s[1024];
    int t = threadIdx.x;
    float acc = 0.f;
    for (int i = t; i < N_SEL; i += 1024) {
        float ap = __uint_as_float(g_ap[i]);
        float an = __uint_as_float(g_an[i]);
        acc += fmaxf(ap - an + 0.5f, 0.f);
    }
    s[t] = acc;
    __syncthreads();
    for (int off = 512; off > 0; off >>= 1) {
        if (t < off) s[t] += s[t + off];
        __syncthreads();
    }
    if (t == 0) out[0] = s[0] * (1.0f / (float)BATCH);
}

// ---------------- launch ----------------
extern "C" void kernel_launch(void* const* d_in, const int* in_sizes, int n_in,
                              void* d_out, int out_size) {
    const float* X  = (const float*)d_in[0];
    const int*   T  = (const int*)d_in[1];
    const int*   UU = (const int*)d_in[2];
    float* out = (float*)d_out;
    (void)in_sizes; (void)n_in; (void)out_size;

    const int TB = 256;
    const int gN = (N_TOT + TB - 1) / TB;
    const int gB = NBUCK / TB;
    const int SMEM_MAIN = (2 * 256 * 64 + 2 * 64) * (int)sizeof(float) + 2 * 64 * (int)sizeof(int);

    cudaFuncSetAttribute(k_main, cudaFuncAttributeMaxDynamicSharedMemorySize, SMEM_MAIN);

    k_init_all<<<gB, TB>>>();

    // shuffle round 1
    k_keys_hist<<<gN, TB>>>(UU, 0);
    k_scanA<<<64, 1024>>>();
    k_scanB<<<1, 64>>>();
    k_scanC<<<64, 1024>>>();
    k_scatter<<<gN, TB>>>(0);
    k_bsort<<<gB, TB>>>(0);

    // shuffle round 2
    k_zero_cnt<<<gB, TB>>>();
    k_keys_hist<<<gN, TB>>>(UU, 1);
    k_scanA<<<64, 1024>>>();
    k_scanB<<<1, 64>>>();
    k_scanC<<<64, 1024>>>();
    k_scatter<<<gN, TB>>>(1);
    k_bsort<<<gB, TB>>>(1);

    // gather + fused gemm/mining + reduce
    k_gather<<<N_SEL, 64>>>(X, T);
    k_main<<<dim3(16, 2, NB), 256, SMEM_MAIN>>>();
    k_reduce<<<1, 1024>>>(out);
}

// round 4
// speedup vs baseline: 1.1018x; 1.1018x over previous
#include <cuda_runtime.h>
#include <math.h>

// ---------------- problem constants ----------------
#define N_TOT   100000
#define N_SEL   5000
#define NB      5
#define BATCH   1000
#define DIMS    256
#define NBUCK   65536
#define CAP     8192                 // candidate cap for top-5000 selection
#define T2CUT   279172874u           // 0.065 * 2^32 ; E[count]=6500, 19-sigma margins both sides
#define STRIDE  258                  // smem row stride (floats): 1032B => conflict-free 8B col loads

// ---------------- scratch ----------------
__device__ unsigned g_key[N_TOT];                 // key1 per element
__device__ unsigned g_keyB[N_TOT], g_valB[N_TOT]; // bucket-scattered (key1, idx)
__device__ unsigned g_cnt[NBUCK], g_start[NBUCK], g_cur[NBUCK];
__device__ unsigned g_bsum[64];
__device__ unsigned long long g_cand[CAP];        // (key2<<32)|q candidates
__device__ unsigned g_ncand;
__device__ unsigned g_qsel[N_SEL];                // q_p : round-1 rank wanted at final pos p
__device__ unsigned g_src[N_SEL];                 // original element index at final pos p
__device__ float    g_X[(size_t)N_SEL * DIMS];
__device__ float    g_sq[N_SEL];
__device__ int      g_lab[N_SEL];
__device__ unsigned g_ap[N_SEL], g_an[N_SEL];

// ---------------- threefry-2x32-20 ----------------
__device__ __forceinline__ void tf2x32(unsigned k0, unsigned k1, unsigned x0, unsigned x1,
                                       unsigned &o0, unsigned &o1) {
    unsigned ks2 = k0 ^ k1 ^ 0x1BD11BDAu;
    x0 += k0; x1 += k1;
#define TFR(r) { x0 += x1; x1 = (x1 << (r)) | (x1 >> (32 - (r))); x1 ^= x0; }
    TFR(13) TFR(15) TFR(26) TFR(6)   x0 += k1;  x1 += ks2 + 1u;
    TFR(17) TFR(29) TFR(16) TFR(24)  x0 += ks2; x1 += k0  + 2u;
    TFR(13) TFR(15) TFR(26) TFR(6)   x0 += k0;  x1 += k1  + 3u;
    TFR(17) TFR(29) TFR(16) TFR(24)  x0 += k1;  x1 += ks2 + 4u;
    TFR(13) TFR(15) TFR(26) TFR(6)   x0 += ks2; x1 += k0  + 5u;
#undef TFR
    o0 = x0; o1 = x1;
}

__device__ __forceinline__ void get_subkey(unsigned uu, int round, unsigned &s0, unsigned &s1) {
    unsigned K0 = 0u, K1 = uu;
    for (int j = 0;; j++) {
        tf2x32(K0, K1, 0u, 1u, s0, s1);
        if (j == round) break;
        unsigned n0, n1; tf2x32(K0, K1, 0u, 0u, n0, n1);
        K0 = n0; K1 = n1;
    }
}

// packed fp32x2 FMA (Blackwell)
__device__ __forceinline__ void fma2(unsigned long long &d, unsigned long long a, unsigned long long b) {
    asm("fma.rn.f32x2 %0, %1, %2, %0;" : "+l"(d) : "l"(a), "l"(b));
}

// ---------------- kernels ----------------
__global__ void k_init() {
    int i = blockIdx.x * blockDim.x + threadIdx.x;
    if (i < NBUCK) g_cnt[i] = 0u;
    if (i < N_SEL) { g_ap[i] = 0u; g_an[i] = 0x7f800000u; }
    if (i < CAP)   g_cand[i] = 0xFFFFFFFFFFFFFFFFull;
    if (i == 0)    g_ncand = 0u;
}

// key1 + key2 in one pass: histogram key1, compact key2 candidates
__global__ void k_keys(const int* uuP) {
    int i = blockIdx.x * blockDim.x + threadIdx.x;
    if (i >= N_TOT) return;
    unsigned uu = (unsigned)uuP[0];
    unsigned s0, s1, t0, t1, o0, o1;
    get_subkey(uu, 0, s0, s1);
    get_subkey(uu, 1, t0, t1);
    unsigned k1, k2;
    tf2x32(s0, s1, 0u, (unsigned)i, o0, o1); k1 = o0;
    tf2x32(t0, t1, 0u, (unsigned)i, o0, o1); k2 = o0;
    g_key[i] = k1;
    atomicAdd(&g_cnt[k1 >> 16], 1u);
    if (k2 < T2CUT) {
        unsigned p = atomicAdd(&g_ncand, 1u);
        if (p < CAP) g_cand[p] = ((unsigned long long)k2 << 32) | (unsigned)i;
    }
}

// scan stage A: per-block exclusive scan of 1024 counters + block sum
__global__ void k_scanA() {
    __shared__ unsigned s[1024];
    int t = threadIdx.x;
    int g = blockIdx.x * 1024 + t;
    unsigned v = g_cnt[g];
    s[t] = v;
    __syncthreads();
    for (int off = 1; off < 1024; off <<= 1) {
        unsigned u = (t >= off) ? s[t - off] : 0u;
        __syncthreads();
        s[t] += u;
        __syncthreads();
    }
    g_start[g] = s[t] - v;
    if (t == 1023) g_bsum[blockIdx.x] = s[t];
}

// scan stage C: add block prefix (computed inline), materialize start/cur
__global__ void k_scanC() {
    unsigned off = 0u;
    for (int j = 0; j < (int)blockIdx.x; j++) off += g_bsum[j];
    int g = blockIdx.x * 1024 + threadIdx.x;
    unsigned st = g_start[g] + off;
    g_start[g] = st;
    g_cur[g]   = st;
}

__global__ void k_scatter() {
    int i = blockIdx.x * blockDim.x + threadIdx.x;
    if (i >= N_TOT) return;
    unsigned k = g_key[i];
    unsigned p = atomicAdd(&g_cur[k >> 16], 1u);
    g_keyB[p] = k; g_valB[p] = (unsigned)i;
}

// exact rank of each candidate among all candidates -> scatter q by rank
__global__ void k_rank() {
    __shared__ unsigned long long s[256];
    int t = blockIdx.x * 256 + threadIdx.x;
    unsigned long long my = g_cand[t];   // padded entries = MAX -> rank >= n >= 5000 -> no write
    unsigned cnt = 0;
    for (int c0 = 0; c0 < CAP; c0 += 256) {
        s[threadIdx.x] = g_cand[c0 + threadIdx.x];
        __syncthreads();
#pragma unroll 8
        for (int j = 0; j < 256; j++) cnt += (s[j] < my) ? 1u : 0u;
        __syncthreads();
    }
    if (cnt < N_SEL) g_qsel[cnt] = (unsigned)(my & 0xFFFFFFFFull);
}

// find element with round-1 rank q (order by (key1, idx)) via bucket selection
__global__ void k_select() {
    int p = blockIdx.x * blockDim.x + threadIdx.x;
    if (p >= N_SEL) return;
    unsigned q = g_qsel[p];
    // last b with g_start[b] <= q
    int lo = 0, hi = NBUCK - 1;
    while (lo < hi) {
        int mid = (lo + hi + 1) >> 1;
        if (g_start[mid] <= q) lo = mid; else hi = mid - 1;
    }
    unsigned base = g_start[lo];
    unsigned n = g_cnt[lo];
    unsigned r = q - base;
    for (unsigned e = 0; e < n; e++) {
        unsigned ke = g_keyB[base + e], ve = g_valB[base + e];
        unsigned rank = 0;
        for (unsigned f = 0; f < n; f++) {
            unsigned kf = g_keyB[base + f], vf = g_valB[base + f];
            rank += (kf < ke || (kf == ke && vf < ve)) ? 1u : 0u;
        }
        if (rank == r) { g_src[p] = ve; break; }
    }
}

// gather selected rows + squared norms + labels
__global__ void k_gather(const float* __restrict__ X, const int* __restrict__ T) {
    int row = blockIdx.x;
    int t = threadIdx.x;    // 64 threads, one float4 each
    unsigned src = g_src[row];
    float4 v = ((const float4*)(X + (size_t)src * DIMS))[t];
    ((float4*)(g_X + (size_t)row * DIMS))[t] = v;
    float ss = v.x * v.x + v.y * v.y + v.z * v.z + v.w * v.w;
    __shared__ float red[64];
    red[t] = ss;
    __syncthreads();
    if (t < 32) {
        float x = red[t] + red[t + 32];
        for (int o = 16; o > 0; o >>= 1) x += __shfl_down_sync(0xffffffffu, x, o);
        if (t == 0) { g_sq[row] = x; g_lab[row] = T[src]; }
    }
}

// persistent fused GEMM (fp32x2 packed FMA) + distance + batch-hard mining
// units: 80 row-tiles x 16 col-tiles (64x64, k=256)
#define NUNITS (80 * 16)
#define PGRID  148
__global__ void k_main() {
    extern __shared__ float sm[];
    float* As  = sm;                       // [64][STRIDE] row-major
    float* Bs  = sm + 64 * STRIDE;
    float* sqA = sm + 2 * 64 * STRIDE;
    float* sqB = sqA + 64;
    int*   labA = (int*)(sqB + 64);
    int*   labB = labA + 64;

    const int tid = threadIdx.x;
    const int tx = tid & 15, ty = tid >> 4;
    const int aOff = (ty * 4) * STRIDE;
    const int bOff = (tx * 4) * STRIDE;

    for (int u = blockIdx.x; u < NUNITS; u += PGRID) {
        const int rt  = u >> 4;
        const int ct  = u & 15;
        const int blk = rt >> 4;
        const int r0  = (rt & 15) * 64;
        const int c0  = ct * 64;
        const int nrows = min(64, BATCH - r0);
        const int ncols = min(64, BATCH - c0);
        const int rowBase = blk * BATCH + r0;
        const int colBase = blk * BATCH + c0;

        __syncthreads();   // protect previous tile use
        for (int idx = tid; idx < 64 * 64; idx += 256) {
            int r = idx >> 6, qq = idx & 63;
            float4 va = make_float4(0.f, 0.f, 0.f, 0.f);
            float4 vb = make_float4(0.f, 0.f, 0.f, 0.f);
            if (r < nrows) va = *(const float4*)&g_X[(size_t)(rowBase + r) * DIMS + qq * 4];
            if (r < ncols) vb = *(const float4*)&g_X[(size_t)(colBase + r) * DIMS + qq * 4];
            float* da = &As[r * STRIDE + qq * 4];
            float* db = &Bs[r * STRIDE + qq * 4];
            *(float2*)da       = make_float2(va.x, va.y);
            *(float2*)(da + 2) = make_float2(va.z, va.w);
            *(float2*)db       = make_float2(vb.x, vb.y);
            *(float2*)(db + 2) = make_float2(vb.z, vb.w);
        }
        if (tid < 64) {
            sqA[tid]  = (tid < nrows) ? g_sq[rowBase + tid] : 0.f;
            labA[tid] = (tid < nrows) ? g_lab[rowBase + tid] : -1;
            sqB[tid]  = (tid < ncols) ? g_sq[colBase + tid] : 0.f;
            labB[tid] = (tid < ncols) ? g_lab[colBase + tid] : 0x7fffffff;
        }
        __syncthreads();

        unsigned long long acc[4][4];
#pragma unroll
        for (int i = 0; i < 4; i++)
#pragma unroll
            for (int j = 0; j < 4; j++) acc[i][j] = 0ull;

#pragma unroll 4
        for (int kk = 0; kk < DIMS / 2; kk++) {
            unsigned long long a0 = *(const unsigned long long*)&As[aOff              + kk * 2];
            unsigned long long a1 = *(const unsigned long long*)&As[aOff + 1 * STRIDE + kk * 2];
            unsigned long long a2 = *(const unsigned long long*)&As[aOff + 2 * STRIDE + kk * 2];
            unsigned long long a3 = *(const unsigned long long*)&As[aOff + 3 * STRIDE + kk * 2];
            unsigned long long b0 = *(const unsigned long long*)&Bs[bOff              + kk * 2];
            unsigned long long b1 = *(const unsigned long long*)&Bs[bOff + 1 * STRIDE + kk * 2];
            unsigned long long b2 = *(const unsigned long long*)&Bs[bOff + 2 * STRIDE + kk * 2];
            unsigned long long b3 = *(const unsigned long long*)&Bs[bOff + 3 * STRIDE + kk * 2];
            fma2(acc[0][0], a0, b0); fma2(acc[0][1], a0, b1); fma2(acc[0][2], a0, b2); fma2(acc[0][3], a0, b3);
            fma2(acc[1][0], a1, b0); fma2(acc[1][1], a1, b1); fma2(acc[1][2], a1, b2); fma2(acc[1][3], a1, b3);
            fma2(acc[2][0], a2, b0); fma2(acc[2][1], a2, b1); fma2(acc[2][2], a2, b2); fma2(acc[2][3], a2, b3);
            fma2(acc[3][0], a3, b0); fma2(acc[3][1], a3, b1); fma2(acc[3][2], a3, b2); fma2(acc[3][3], a3, b3);
        }

        // epilogue: distance + batch-hard partials
        float rmax[4], rmin[4];
#pragma unroll
        for (int i = 0; i < 4; i++) { rmax[i] = 0.f; rmin[i] = __uint_as_float(0x7f800000u); }
#pragma unroll
        for (int i = 0; i < 4; i++) {
            int gr = ty * 4 + i;
            float sqi = sqA[gr];
            int   li  = labA[gr];
#pragma unroll
            for (int j = 0; j < 4; j++) {
                int gc = tx * 4 + j;
                float2 pr = *(float2*)&acc[i][j];
                float g = pr.x + pr.y;
                if (gr < nrows && gc < ncols) {
                    float d2 = sqi + sqB[gc] - 2.f * g;
                    float dist = sqrtf(fmaxf(d2, 1e-12f));
                    if (li == labB[gc]) rmax[i] = fmaxf(rmax[i], dist);
                    else                rmin[i] = fminf(rmin[i], dist);
                }
            }
        }
        // reduce across the 16 tx lanes sharing each row group
#pragma unroll
        for (int off = 1; off < 16; off <<= 1) {
#pragma unroll
            for (int i = 0; i < 4; i++) {
                rmax[i] = fmaxf(rmax[i], __shfl_xor_sync(0xffffffffu, rmax[i], off));
                rmin[i] = fminf(rmin[i], __shfl_xor_sync(0xffffffffu, rmin[i], off));
            }
        }
        if (tx == 0) {
#pragma unroll
            for (int i = 0; i < 4; i++) {
                int gr = ty * 4 + i;
                if (gr < nrows) {
                    atomicMax(&g_ap[rowBase + gr], __float_as_uint(rmax[i]));
                    atomicMin(&g_an[rowBase + gr], __float_as_uint(rmin[i]));
                }
            }
        }
    }
}

__global__ void k_reduce(float* __restrict__ out) {
    __shared__ float s[1024];
    int t = threadIdx.x;
    float acc = 0.f;
    for (int i = t; i < N_SEL; i += 1024) {
        float ap = __uint_as_float(g_ap[i]);
        float an = __uint_as_float(g_an[i]);
        acc += fmaxf(ap - an + 0.5f, 0.f);
    }
    s[t] = acc;
    __syncthreads();
    for (int off = 512; off > 0; off >>= 1) {
        if (t < off) s[t] += s[t + off];
        __syncthreads();
    }
    if (t == 0) out[0] = s[0] * (1.0f / (float)BATCH);
}

// ---------------- launch ----------------
extern "C" void kernel_launch(void* const* d_in, const int* in_sizes, int n_in,
                              void* d_out, int out_size) {
    const float* X  = (const float*)d_in[0];
    const int*   T  = (const int*)d_in[1];
    const int*   UU = (const int*)d_in[2];
    float* out = (float*)d_out;
    (void)in_sizes; (void)n_in; (void)out_size;

    const int TB = 256;
    const int gN = (N_TOT + TB - 1) / TB;
    const int gB = NBUCK / TB;
    const int SMEM_MAIN = (2 * 64 * STRIDE + 2 * 64) * (int)sizeof(float) + 2 * 64 * (int)sizeof(int);

    cudaFuncSetAttribute(k_main, cudaFuncAttributeMaxDynamicSharedMemorySize, SMEM_MAIN);

    k_init<<<gB, TB>>>();
    k_keys<<<gN, TB>>>(UU);
    k_scanA<<<64, 1024>>>();
    k_scanC<<<64, 1024>>>();
    k_scatter<<<gN, TB>>>();
    k_rank<<<CAP / 256, 256>>>();
    k_select<<<(N_SEL + TB - 1) / TB, TB>>>();
    k_gather<<<N_SEL, 64>>>(X, T);
    k_main<<<PGRID, 256, SMEM_MAIN>>>();
    k_reduce<<<1, 1024>>>(out);
}

// round 5
// speedup vs baseline: 1.5713x; 1.4262x over previous
#include <cuda_runtime.h>
#include <math.h>

// ---------------- problem constants ----------------
#define N_TOT   100000
#define N_SEL   5000
#define NB      5
#define BATCH   1000
#define DIMS    256
#define NBUCK   65536
#define CAP     8192                 // candidate cap for top-5000 selection
#define T2CUT   279172874u           // 0.065 * 2^32 ; E[count]=6500, 19-sigma margins both sides

// ---------------- scratch ----------------
__device__ unsigned g_key[N_TOT];
__device__ unsigned g_keyB[N_TOT], g_valB[N_TOT];
__device__ unsigned g_cnt[NBUCK], g_start[NBUCK], g_cur[NBUCK];
__device__ unsigned g_bsum[64];
__device__ unsigned long long g_cand[CAP];        // (key2<<32)|idx candidates
__device__ unsigned g_ncand;
__device__ unsigned g_qsel[N_SEL];
__device__ unsigned g_src[N_SEL];
__device__ float    g_X[(size_t)N_SEL * DIMS];
__device__ float    g_sq[N_SEL];
__device__ int      g_lab[N_SEL];
__device__ unsigned g_ap[N_SEL], g_an[N_SEL];

// ---------------- threefry-2x32-20 ----------------
__device__ __forceinline__ void tf2x32(unsigned k0, unsigned k1, unsigned x0, unsigned x1,
                                       unsigned &o0, unsigned &o1) {
    unsigned ks2 = k0 ^ k1 ^ 0x1BD11BDAu;
    x0 += k0; x1 += k1;
#define TFR(r) { x0 += x1; x1 = (x1 << (r)) | (x1 >> (32 - (r))); x1 ^= x0; }
    TFR(13) TFR(15) TFR(26) TFR(6)   x0 += k1;  x1 += ks2 + 1u;
    TFR(17) TFR(29) TFR(16) TFR(24)  x0 += ks2; x1 += k0  + 2u;
    TFR(13) TFR(15) TFR(26) TFR(6)   x0 += k0;  x1 += k1  + 3u;
    TFR(17) TFR(29) TFR(16) TFR(24)  x0 += k1;  x1 += ks2 + 4u;
    TFR(13) TFR(15) TFR(26) TFR(6)   x0 += ks2; x1 += k0  + 5u;
#undef TFR
    o0 = x0; o1 = x1;
}

__device__ __forceinline__ void get_subkey(unsigned uu, int round, unsigned &s0, unsigned &s1) {
    unsigned K0 = 0u, K1 = uu;
    for (int j = 0;; j++) {
        tf2x32(K0, K1, 0u, 1u, s0, s1);
        if (j == round) break;
        unsigned n0, n1; tf2x32(K0, K1, 0u, 0u, n0, n1);
        K0 = n0; K1 = n1;
    }
}

__device__ __forceinline__ void fma2(unsigned long long &d, unsigned long long a, unsigned long long b) {
    asm("fma.rn.f32x2 %0, %1, %2, %0;" : "+l"(d) : "l"(a), "l"(b));
}
__device__ __forceinline__ float unpack_sum(unsigned long long v) {
    float lo, hi;
    asm("mov.b64 {%0, %1}, %2;" : "=f"(lo), "=f"(hi) : "l"(v));
    return lo + hi;
}

// ---------------- kernels ----------------
__global__ void k_init() {
    int i = blockIdx.x * blockDim.x + threadIdx.x;
    if (i < NBUCK) g_cnt[i] = 0u;
    if (i < N_SEL) { g_ap[i] = 0u; g_an[i] = 0x7f800000u; }
    if (i < CAP)   g_cand[i] = 0xFFFFFFFFFFFFFFFFull;
    if (i == 0)    g_ncand = 0u;
}

__global__ void k_keys(const int* uuP) {
    int i = blockIdx.x * blockDim.x + threadIdx.x;
    if (i >= N_TOT) return;
    unsigned uu = (unsigned)uuP[0];
    unsigned s0, s1, t0, t1, o0, o1;
    get_subkey(uu, 0, s0, s1);
    get_subkey(uu, 1, t0, t1);
    unsigned k1, k2;
    tf2x32(s0, s1, 0u, (unsigned)i, o0, o1); k1 = o0;
    tf2x32(t0, t1, 0u, (unsigned)i, o0, o1); k2 = o0;
    g_key[i] = k1;
    atomicAdd(&g_cnt[k1 >> 16], 1u);
    if (k2 < T2CUT) {
        unsigned p = atomicAdd(&g_ncand, 1u);
        if (p < CAP) g_cand[p] = ((unsigned long long)k2 << 32) | (unsigned)i;
    }
}

__global__ void k_scanA() {
    __shared__ unsigned s[1024];
    int t = threadIdx.x;
    int g = blockIdx.x * 1024 + t;
    unsigned v = g_cnt[g];
    s[t] = v;
    __syncthreads();
    for (int off = 1; off < 1024; off <<= 1) {
        unsigned u = (t >= off) ? s[t - off] : 0u;
        __syncthreads();
        s[t] += u;
        __syncthreads();
    }
    g_start[g] = s[t] - v;
    if (t == 1023) g_bsum[blockIdx.x] = s[t];
}

__global__ void k_scanC() {
    __shared__ unsigned s[64];
    int t = threadIdx.x;
    if (t < 64) s[t] = g_bsum[t];
    __syncthreads();
    for (int off = 1; off < 64; off <<= 1) {
        unsigned u = (t < 64 && t >= off) ? s[t - off] : 0u;
        __syncthreads();
        if (t < 64) s[t] += u;
        __syncthreads();
    }
    unsigned off = (blockIdx.x == 0) ? 0u : s[blockIdx.x - 1];
    int g = blockIdx.x * 1024 + t;
    unsigned st = g_start[g] + off;
    g_start[g] = st;
    g_cur[g]   = st;
}

__global__ void k_scatter() {
    int i = blockIdx.x * blockDim.x + threadIdx.x;
    if (i >= N_TOT) return;
    unsigned k = g_key[i];
    unsigned p = atomicAdd(&g_cur[k >> 16], 1u);
    g_keyB[p] = k; g_valB[p] = (unsigned)i;
}

// warp-per-candidate exact rank; coalesced sweep; full-chip
__global__ void k_rank() {
    int c = blockIdx.x * 8 + (threadIdx.x >> 5);
    int lane = threadIdx.x & 31;
    unsigned long long my = g_cand[c];
    unsigned cnt = 0;
    for (int j = lane; j < CAP; j += 32)
        cnt += (g_cand[j] < my) ? 1u : 0u;
#pragma unroll
    for (int o = 16; o > 0; o >>= 1) cnt += __shfl_xor_sync(0xffffffffu, cnt, o);
    if (lane == 0 && cnt < N_SEL) g_qsel[cnt] = (unsigned)(my & 0xFFFFFFFFull);
}

__global__ void k_select() {
    int p = blockIdx.x * blockDim.x + threadIdx.x;
    if (p >= N_SEL) return;
    unsigned q = g_qsel[p];
    int lo = 0, hi = NBUCK - 1;
    while (lo < hi) {
        int mid = (lo + hi + 1) >> 1;
        if (g_start[mid] <= q) lo = mid; else hi = mid - 1;
    }
    unsigned base = g_start[lo];
    unsigned n = g_cnt[lo];
    unsigned r = q - base;
    for (unsigned e = 0; e < n; e++) {
        unsigned ke = g_keyB[base + e], ve = g_valB[base + e];
        unsigned rank = 0;
        for (unsigned f = 0; f < n; f++) {
            unsigned kf = g_keyB[base + f], vf = g_valB[base + f];
            rank += (kf < ke || (kf == ke && vf < ve)) ? 1u : 0u;
        }
        if (rank == r) { g_src[p] = ve; break; }
    }
}

__global__ void k_gather(const float* __restrict__ X, const int* __restrict__ T) {
    int row = blockIdx.x;
    int t = threadIdx.x;    // 64 threads, one float4 each
    unsigned src = g_src[row];
    float4 v = ((const float4*)(X + (size_t)src * DIMS))[t];
    ((float4*)(g_X + (size_t)row * DIMS))[t] = v;
    float ss = v.x * v.x + v.y * v.y + v.z * v.z + v.w * v.w;
    __shared__ float red[64];
    red[t] = ss;
    __syncthreads();
    if (t < 32) {
        float x = red[t] + red[t + 32];
        for (int o = 16; o > 0; o >>= 1) x += __shfl_down_sync(0xffffffffu, x, o);
        if (t == 0) { g_sq[row] = x; g_lab[row] = T[src]; }
    }
}

// persistent fused GEMM (k-pair-major float2 tiles, strided microtile, f32x2 FMA)
#define NUNITS (80 * 16)
#define PGRID  148
__global__ void k_main() {
    extern __shared__ float sm[];
    float2* As2 = (float2*)sm;                 // [128][64] : (kk, row) -> (x[2kk], x[2kk+1])
    float2* Bs2 = As2 + 128 * 64;
    float*  sqA = (float*)(Bs2 + 128 * 64);
    float*  sqB = sqA + 64;
    int*    labA = (int*)(sqB + 64);
    int*    labB = labA + 64;

    const int tid = threadIdx.x;
    const int tx = tid & 15, ty = tid >> 4;

    for (int u = blockIdx.x; u < NUNITS; u += PGRID) {
        const int rt  = u >> 4;
        const int ct  = u & 15;
        const int blk = rt >> 4;
        const int r0  = (rt & 15) * 64;
        const int c0  = ct * 64;
        const int nrows = min(64, BATCH - r0);
        const int ncols = min(64, BATCH - c0);
        const int rowBase = blk * BATCH + r0;
        const int colBase = blk * BATCH + c0;

        __syncthreads();
        // load tiles: warp = 32 consecutive rows, one float4 (4 k) per thread
        for (int idx = tid; idx < 64 * 64; idx += 256) {
            int r = idx & 63, qq = idx >> 6;     // qq: float4 chunk (k = 4qq..4qq+3)
            float4 va = make_float4(0.f, 0.f, 0.f, 0.f);
            float4 vb = make_float4(0.f, 0.f, 0.f, 0.f);
            if (r < nrows) va = *(const float4*)&g_X[(size_t)(rowBase + r) * DIMS + qq * 4];
            if (r < ncols) vb = *(const float4*)&g_X[(size_t)(colBase + r) * DIMS + qq * 4];
            As2[(2 * qq)     * 64 + r] = make_float2(va.x, va.y);
            As2[(2 * qq + 1) * 64 + r] = make_float2(va.z, va.w);
            Bs2[(2 * qq)     * 64 + r] = make_float2(vb.x, vb.y);
            Bs2[(2 * qq + 1) * 64 + r] = make_float2(vb.z, vb.w);
        }
        if (tid < 64) {
            sqA[tid]  = (tid < nrows) ? g_sq[rowBase + tid] : 0.f;
            labA[tid] = (tid < nrows) ? g_lab[rowBase + tid] : -1;
            sqB[tid]  = (tid < ncols) ? g_sq[colBase + tid] : 0.f;
            labB[tid] = (tid < ncols) ? g_lab[colBase + tid] : 0x7fffffff;
        }
        __syncthreads();

        // thread (tx,ty) owns rows {2ty,2ty+1,2ty+32,2ty+33} x cols {2tx,2tx+1,2tx+32,2tx+33}
        unsigned long long acc[4][4];
#pragma unroll
        for (int i = 0; i < 4; i++)
#pragma unroll
            for (int j = 0; j < 4; j++) acc[i][j] = 0ull;

#pragma unroll 4
        for (int kk = 0; kk < 128; kk++) {
            ulonglong2 a0 = *(const ulonglong2*)&As2[kk * 64 + 2 * ty];        // rows 2ty, 2ty+1
            ulonglong2 a1 = *(const ulonglong2*)&As2[kk * 64 + 2 * ty + 32];   // rows 2ty+32, 2ty+33
            ulonglong2 b0 = *(const ulonglong2*)&Bs2[kk * 64 + 2 * tx];        // cols 2tx, 2tx+1
            ulonglong2 b1 = *(const ulonglong2*)&Bs2[kk * 64 + 2 * tx + 32];   // cols 2tx+32, 2tx+33
            fma2(acc[0][0], a0.x, b0.x); fma2(acc[0][1], a0.x, b0.y); fma2(acc[0][2], a0.x, b1.x); fma2(acc[0][3], a0.x, b1.y);
            fma2(acc[1][0], a0.y, b0.x); fma2(acc[1][1], a0.y, b0.y); fma2(acc[1][2], a0.y, b1.x); fma2(acc[1][3], a0.y, b1.y);
            fma2(acc[2][0], a1.x, b0.x); fma2(acc[2][1], a1.x, b0.y); fma2(acc[2][2], a1.x, b1.x); fma2(acc[2][3], a1.x, b1.y);
            fma2(acc[3][0], a1.y, b0.x); fma2(acc[3][1], a1.y, b0.y); fma2(acc[3][2], a1.y, b1.x); fma2(acc[3][3], a1.y, b1.y);
        }

        // epilogue
        float rmax[4], rmin[4];
#pragma unroll
        for (int i = 0; i < 4; i++) { rmax[i] = 0.f; rmin[i] = __uint_as_float(0x7f800000u); }
#pragma unroll
        for (int i = 0; i < 4; i++) {
            int gr = 2 * ty + (i & 1) + (i >> 1) * 32;
            float sqi = sqA[gr];
            int   li  = labA[gr];
#pragma unroll
            for (int j = 0; j < 4; j++) {
                int gc = 2 * tx + (j & 1) + (j >> 1) * 32;
                if (gr < nrows && gc < ncols) {
                    float g = unpack_sum(acc[i][j]);
                    float d2 = sqi + sqB[gc] - 2.f * g;
                    float dist = sqrtf(fmaxf(d2, 1e-12f));
                    if (li == labB[gc]) rmax[i] = fmaxf(rmax[i], dist);
                    else                rmin[i] = fminf(rmin[i], dist);
                }
            }
        }
        // reduce across the 16 tx lanes (each half-warp shares ty)
#pragma unroll
        for (int off = 1; off < 16; off <<= 1) {
#pragma unroll
            for (int i = 0; i < 4; i++) {
                rmax[i] = fmaxf(rmax[i], __shfl_xor_sync(0xffffffffu, rmax[i], off));
                rmin[i] = fminf(rmin[i], __shfl_xor_sync(0xffffffffu, rmin[i], off));
            }
        }
        if (tx == 0) {
#pragma unroll
            for (int i = 0; i < 4; i++) {
                int gr = 2 * ty + (i & 1) + (i >> 1) * 32;
                if (gr < nrows) {
                    atomicMax(&g_ap[rowBase + gr], __float_as_uint(rmax[i]));
                    atomicMin(&g_an[rowBase + gr], __float_as_uint(rmin[i]));
                }
            }
        }
    }
}

__global__ void k_reduce(float* __restrict__ out) {
    __shared__ float s[1024];
    int t = threadIdx.x;
    float acc = 0.f;
    for (int i = t; i < N_SEL; i += 1024) {
        float ap = __uint_as_float(g_ap[i]);
        float an = __uint_as_float(g_an[i]);
        acc += fmaxf(ap - an + 0.5f, 0.f);
    }
    s[t] = acc;
    __syncthreads();
    for (int off = 512; off > 0; off >>= 1) {
        if (t < off) s[t] += s[t + off];
        __syncthreads();
    }
    if (t == 0) out[0] = s[0] * (1.0f / (float)BATCH);
}

// ---------------- launch ----------------
extern "C" void kernel_launch(void* const* d_in, const int* in_sizes, int n_in,
                              void* d_out, int out_size) {
    const float* X  = (const float*)d_in[0];
    const int*   T  = (const int*)d_in[1];
    const int*   UU = (const int*)d_in[2];
    float* out = (float*)d_out;
    (void)in_sizes; (void)n_in; (void)out_size;

    const int TB = 256;
    const int gN = (N_TOT + TB - 1) / TB;
    const int gB = NBUCK / TB;
    const int SMEM_MAIN = (2 * 128 * 64) * (int)sizeof(float2) + 2 * 64 * (int)sizeof(float) + 2 * 64 * (int)sizeof(int);

    cudaFuncSetAttribute(k_main, cudaFuncAttributeMaxDynamicSharedMemorySize, SMEM_MAIN);

    k_init<<<gB, TB>>>();
    k_keys<<<gN, TB>>>(UU);
    k_scanA<<<64, 1024>>>();
    k_scanC<<<64, 1024>>>();
    k_scatter<<<gN, TB>>>();
    k_rank<<<CAP / 8, 256>>>();
    k_select<<<(N_SEL + TB - 1) / TB, TB>>>();
    k_gather<<<N_SEL, 64>>>(X, T);
    k_main<<<PGRID, 256, SMEM_MAIN>>>();
    k_reduce<<<1, 1024>>>(out);
}

// round 6
// speedup vs baseline: 1.8745x; 1.1930x over previous
#include <cuda_runtime.h>
#include <math.h>

// ---------------- problem constants ----------------
#define N_TOT   100000
#define N_SEL   5000
#define NB      5
#define BATCH   1000
#define DIMS    256
#define NBUCK   65536
#define CAP     8192
#define T2CUT   279172874u           // 0.065 * 2^32 ; E[count]=6500, 19-sigma margins
#define RDIV    1090520u             // ceil(T2CUT/256): bucket divisor for rank
#define KCH     64                   // k-pairs per chunk (2 chunks of 128 k)

// ---------------- scratch ----------------
__device__ unsigned g_key[N_TOT];
__device__ unsigned g_keyB[N_TOT], g_valB[N_TOT];
__device__ unsigned g_cnt[NBUCK], g_start[NBUCK], g_cur[NBUCK];
__device__ unsigned g_bsum[64];
__device__ unsigned g_bar;
__device__ unsigned long long g_cand[CAP];
__device__ unsigned g_ncand;
__device__ unsigned g_qsel[N_SEL];
__device__ unsigned g_src[N_SEL];
__device__ float    g_X[(size_t)N_SEL * DIMS];
__device__ float    g_sq[N_SEL];
__device__ int      g_lab[N_SEL];
__device__ unsigned g_ap[N_SEL], g_an[N_SEL];   // d^2 bits (clamped positive)

// ---------------- threefry-2x32-20 ----------------
__device__ __forceinline__ void tf2x32(unsigned k0, unsigned k1, unsigned x0, unsigned x1,
                                       unsigned &o0, unsigned &o1) {
    unsigned ks2 = k0 ^ k1 ^ 0x1BD11BDAu;
    x0 += k0; x1 += k1;
#define TFR(r) { x0 += x1; x1 = (x1 << (r)) | (x1 >> (32 - (r))); x1 ^= x0; }
    TFR(13) TFR(15) TFR(26) TFR(6)   x0 += k1;  x1 += ks2 + 1u;
    TFR(17) TFR(29) TFR(16) TFR(24)  x0 += ks2; x1 += k0  + 2u;
    TFR(13) TFR(15) TFR(26) TFR(6)   x0 += k0;  x1 += k1  + 3u;
    TFR(17) TFR(29) TFR(16) TFR(24)  x0 += k1;  x1 += ks2 + 4u;
    TFR(13) TFR(15) TFR(26) TFR(6)   x0 += ks2; x1 += k0  + 5u;
#undef TFR
    o0 = x0; o1 = x1;
}

__device__ __forceinline__ void get_subkey(unsigned uu, int round, unsigned &s0, unsigned &s1) {
    unsigned K0 = 0u, K1 = uu;
    for (int j = 0;; j++) {
        tf2x32(K0, K1, 0u, 1u, s0, s1);
        if (j == round) break;
        unsigned n0, n1; tf2x32(K0, K1, 0u, 0u, n0, n1);
        K0 = n0; K1 = n1;
    }
}

__device__ __forceinline__ void fma2(unsigned long long &d, unsigned long long a, unsigned long long b) {
    asm("fma.rn.f32x2 %0, %1, %2, %0;" : "+l"(d) : "l"(a), "l"(b));
}
__device__ __forceinline__ float unpack_sum(unsigned long long v) {
    float lo, hi;
    asm("mov.b64 {%0, %1}, %2;" : "=f"(lo), "=f"(hi) : "l"(v));
    return lo + hi;
}

// ---------------- kernels ----------------
__global__ void k_init() {
    int i = blockIdx.x * blockDim.x + threadIdx.x;
    if (i < NBUCK) g_cnt[i] = 0u;
    if (i < N_SEL) { g_ap[i] = 0u; g_an[i] = 0x7f800000u; }
    if (i < CAP)   g_cand[i] = 0xFFFFFFFFFFFFFFFFull;
    if (i == 0)    { g_ncand = 0u; g_bar = 0u; }
}

__global__ void k_keys(const int* uuP) {
    int i = blockIdx.x * blockDim.x + threadIdx.x;
    if (i >= N_TOT) return;
    unsigned uu = (unsigned)uuP[0];
    unsigned s0, s1, t0, t1, o0, o1;
    get_subkey(uu, 0, s0, s1);
    get_subkey(uu, 1, t0, t1);
    unsigned k1, k2;
    tf2x32(s0, s1, 0u, (unsigned)i, o0, o1); k1 = o0;
    tf2x32(t0, t1, 0u, (unsigned)i, o0, o1); k2 = o0;
    g_key[i] = k1;
    atomicAdd(&g_cnt[k1 >> 16], 1u);
    if (k2 < T2CUT) {
        unsigned p = atomicAdd(&g_ncand, 1u);
        if (p < CAP) g_cand[p] = ((unsigned long long)k2 << 32) | (unsigned)i;
    }
}

// fused grid-wide exclusive scan of 65536 counters (64 all-resident blocks + grid barrier)
__global__ void k_scan() {
    __shared__ unsigned s[1024];
    __shared__ unsigned sb[64];
    int t = threadIdx.x;
    int g = blockIdx.x * 1024 + t;
    unsigned v = g_cnt[g];
    s[t] = v;
    __syncthreads();
    for (int off = 1; off < 1024; off <<= 1) {
        unsigned u = (t >= off) ? s[t - off] : 0u;
        __syncthreads();
        s[t] += u;
        __syncthreads();
    }
    unsigned excl = s[t] - v;
    if (t == 1023) g_bsum[blockIdx.x] = s[t];
    __threadfence();
    __syncthreads();
    if (t == 0) {
        atomicAdd(&g_bar, 1u);
        while (atomicAdd(&g_bar, 0u) < 64u) {}
    }
    __syncthreads();
    if (t < 64) sb[t] = ((volatile unsigned*)g_bsum)[t];
    __syncthreads();
    if (t < 64) {
        for (int off = 1; off < 64; off <<= 1) {
            unsigned u = (t >= off) ? sb[t - off] : 0u;
            __syncthreads();
            sb[t] += u;
            __syncthreads();
        }
    } else {
        for (int off = 1; off < 64; off <<= 1) { __syncthreads(); __syncthreads(); }
    }
    unsigned boff = (blockIdx.x == 0) ? 0u : sb[blockIdx.x - 1];
    unsigned st = excl + boff;
    g_start[g] = st;
    g_cur[g]   = st;
}

__global__ void k_scatter() {
    int i = blockIdx.x * blockDim.x + threadIdx.x;
    if (i >= N_TOT) return;
    unsigned k = g_key[i];
    unsigned p = atomicAdd(&g_cur[k >> 16], 1u);
    g_keyB[p] = k; g_valB[p] = (unsigned)i;
}

// single-block bucketed exact rank of candidates (order = (key2, idx) ascending)
__global__ void k_rank() {
    extern __shared__ unsigned long long sc[];            // [CAP] scattered candidates
    __shared__ unsigned hist[256], hscan[256], cur[256];
    int t = threadIdx.x;
    for (int i = t; i < 256; i += 1024) hist[i] = 0u;
    __syncthreads();
    // pass 1: histogram
    for (int c = t; c < CAP; c += 1024) {
        unsigned k2 = (unsigned)(g_cand[c] >> 32);
        unsigned b = min(k2 / RDIV, 255u);
        atomicAdd(&hist[b], 1u);
    }
    __syncthreads();
    // scan hist (256 lanes active)
    if (t < 256) hscan[t] = hist[t];
    __syncthreads();
    for (int off = 1; off < 256; off <<= 1) {
        unsigned u = (t < 256 && t >= off) ? hscan[t - off] : 0u;
        __syncthreads();
        if (t < 256) hscan[t] += u;
        __syncthreads();
    }
    if (t < 256) cur[t] = hscan[t] - hist[t];            // exclusive
    __syncthreads();
    // pass 2: scatter into smem by bucket
    for (int c = t; c < CAP; c += 1024) {
        unsigned long long v = g_cand[c];
        unsigned b = min((unsigned)(v >> 32) / RDIV, 255u);
        unsigned p = atomicAdd(&cur[b], 1u);
        sc[p] = v;
    }
    __syncthreads();
    // pass 3: rank within bucket
    for (int c = t; c < CAP; c += 1024) {
        unsigned long long v = sc[c];
        unsigned k2 = (unsigned)(v >> 32);
        if (k2 >= T2CUT) continue;                        // padding
        unsigned b = min(k2 / RDIV, 255u);
        unsigned s0 = (b == 0) ? 0u : hscan[b - 1];
        unsigned e0 = hscan[b];
        unsigned r = s0;
        for (unsigned j = s0; j < e0; j++) r += (sc[j] < v) ? 1u : 0u;
        if (r < N_SEL) g_qsel[r] = (unsigned)(v & 0xFFFFFFFFull);
    }
}

__global__ void k_select() {
    int p = blockIdx.x * blockDim.x + threadIdx.x;
    if (p >= N_SEL) return;
    unsigned q = g_qsel[p];
    int lo = 0, hi = NBUCK - 1;
    while (lo < hi) {
        int mid = (lo + hi + 1) >> 1;
        if (g_start[mid] <= q) lo = mid; else hi = mid - 1;
    }
    unsigned base = g_start[lo];
    unsigned n = g_cnt[lo];
    unsigned r = q - base;
    for (unsigned e = 0; e < n; e++) {
        unsigned ke = g_keyB[base + e], ve = g_valB[base + e];
        unsigned rank = 0;
        for (unsigned f = 0; f < n; f++) {
            unsigned kf = g_keyB[base + f], vf = g_valB[base + f];
            rank += (kf < ke || (kf == ke && vf < ve)) ? 1u : 0u;
        }
        if (rank == r) { g_src[p] = ve; break; }
    }
}

__global__ void k_gather(const float* __restrict__ X, const int* __restrict__ T) {
    int row = blockIdx.x;
    int t = threadIdx.x;
    unsigned src = g_src[row];
    float4 v = ((const float4*)(X + (size_t)src * DIMS))[t];
    ((float4*)(g_X + (size_t)row * DIMS))[t] = v;
    float ss = v.x * v.x + v.y * v.y + v.z * v.z + v.w * v.w;
    __shared__ float red[64];
    red[t] = ss;
    __syncthreads();
    if (t < 32) {
        float x = red[t] + red[t + 32];
        for (int o = 16; o > 0; o >>= 1) x += __shfl_down_sync(0xffffffffu, x, o);
        if (t == 0) { g_sq[row] = x; g_lab[row] = T[src]; }
    }
}

// persistent fused symmetric GEMM + batch-hard mining on d^2
// units: 5 blocks x 136 upper-triangle tile pairs (64x64 tiles); 64-thr CTAs, 8x8 microtile
#define NUNITS (NB * 136)
#define PGRID  (148 * 3)
__global__ void __launch_bounds__(64, 3) k_main() {
    extern __shared__ float smf[];
    unsigned long long* AsU = (unsigned long long*)smf;          // [KCH][64] k-pair-major
    unsigned long long* BsU = AsU + KCH * 64;
    float* sqA = (float*)(BsU + KCH * 64);
    float* sqB = sqA + 64;
    int* labA = (int*)(sqB + 64);
    int* labB = labA + 64;

    const int tid = threadIdx.x;
    const int tx = tid & 7, ty = tid >> 3;     // 8 col-groups x 8 row-groups

    for (int u = blockIdx.x; u < NUNITS; u += PGRID) {
        int blk = u / 136;
        int s = u - blk * 136;
        int rt = 0, rem = s;
        while (rem >= 16 - rt) { rem -= 16 - rt; rt++; }
        int ct = rt + rem;
        const int r0 = rt * 64, c0 = ct * 64;
        const int nrows = min(64, BATCH - r0);
        const int ncols = min(64, BATCH - c0);
        const int rowBase = blk * BATCH + r0;
        const int colBase = blk * BATCH + c0;

        unsigned long long acc[8][8];
#pragma unroll
        for (int i = 0; i < 8; i++)
#pragma unroll
            for (int j = 0; j < 8; j++) acc[i][j] = 0ull;

        __syncthreads();   // protect sq/lab of previous unit
        if (tid < 64) {
            sqA[tid]  = (tid < nrows) ? g_sq[rowBase + tid] : 0.f;
            labA[tid] = (tid < nrows) ? g_lab[rowBase + tid] : -1;
            sqB[tid]  = (tid < ncols) ? g_sq[colBase + tid] : 0.f;
            labB[tid] = (tid < ncols) ? g_lab[colBase + tid] : -2;
        }

        for (int ch = 0; ch < 2; ch++) {
            __syncthreads();
            // load chunk: 64 rows x 32 float4 (=128 k) per matrix
            for (int idx = tid; idx < 64 * 32; idx += 64) {
                int r = idx >> 5, q = idx & 31;
                float4 va = make_float4(0.f, 0.f, 0.f, 0.f);
                float4 vb = make_float4(0.f, 0.f, 0.f, 0.f);
                if (r < nrows) va = *(const float4*)&g_X[(size_t)(rowBase + r) * DIMS + ch * 128 + q * 4];
                if (r < ncols) vb = *(const float4*)&g_X[(size_t)(colBase + r) * DIMS + ch * 128 + q * 4];
                float2* a0 = (float2*)&AsU[(2 * q)     * 64 + r];
                float2* a1 = (float2*)&AsU[(2 * q + 1) * 64 + r];
                float2* b0 = (float2*)&BsU[(2 * q)     * 64 + r];
                float2* b1 = (float2*)&BsU[(2 * q + 1) * 64 + r];
                *a0 = make_float2(va.x, va.y); *a1 = make_float2(va.z, va.w);
                *b0 = make_float2(vb.x, vb.y); *b1 = make_float2(vb.z, vb.w);
            }
            __syncthreads();

            const ulonglong2* AsU2 = (const ulonglong2*)AsU;
#pragma unroll 2
            for (int kk = 0; kk < KCH; kk++) {
                ulonglong2 p0 = AsU2[kk * 32 + 2 * ty];        // rows 4ty, 4ty+1
                ulonglong2 p1 = AsU2[kk * 32 + 2 * ty + 1];    // rows 4ty+2, 4ty+3
                ulonglong2 p2 = AsU2[kk * 32 + 2 * ty + 16];   // rows 4ty+32, +33
                ulonglong2 p3 = AsU2[kk * 32 + 2 * ty + 17];   // rows 4ty+34, +35
                unsigned long long A[8] = {p0.x, p0.y, p1.x, p1.y, p2.x, p2.y, p3.x, p3.y};
                unsigned long long Bv[8];
#pragma unroll
                for (int j = 0; j < 8; j++) Bv[j] = BsU[kk * 64 + tx + 8 * j];
#pragma unroll
                for (int i = 0; i < 8; i++)
#pragma unroll
                    for (int j = 0; j < 8; j++) fma2(acc[i][j], A[i], Bv[j]);
            }
        }

        // epilogue on d^2 (sqrt deferred; max/min commute with sqrt(clip))
        float rP[8], rN[8], cP[8], cN[8];
#pragma unroll
        for (int i = 0; i < 8; i++) { rP[i] = 0.f; rN[i] = __uint_as_float(0x7f800000u); }
#pragma unroll
        for (int j = 0; j < 8; j++) { cP[j] = 0.f; cN[j] = __uint_as_float(0x7f800000u); }

#pragma unroll
        for (int i = 0; i < 8; i++) {
            int row = 4 * ty + (i & 3) + (i >> 2) * 32;
            float sqi = sqA[row];
            int   li  = labA[row];
            bool  vr  = row < nrows;
#pragma unroll
            for (int j = 0; j < 8; j++) {
                int col = tx + 8 * j;
                if (vr && col < ncols) {
                    float g = unpack_sum(acc[i][j]);
                    float d2 = fmaxf(sqi + sqB[col] - 2.f * g, 1e-12f);
                    if (li == labB[col]) { rP[i] = fmaxf(rP[i], d2); cP[j] = fmaxf(cP[j], d2); }
                    else                 { rN[i] = fminf(rN[i], d2); cN[j] = fminf(cN[j], d2); }
                }
            }
        }
        // row stats: reduce over tx octet (lanes sharing ty)
#pragma unroll
        for (int o = 1; o < 8; o <<= 1) {
#pragma unroll
            for (int i = 0; i < 8; i++) {
                rP[i] = fmaxf(rP[i], __shfl_xor_sync(0xffffffffu, rP[i], o));
                rN[i] = fminf(rN[i], __shfl_xor_sync(0xffffffffu, rN[i], o));
            }
        }
        // col stats: reduce over ty (xor 8, 16 within warp; two warps both contribute via atomics)
#pragma unroll
        for (int o = 8; o < 32; o <<= 1) {
#pragma unroll
            for (int j = 0; j < 8; j++) {
                cP[j] = fmaxf(cP[j], __shfl_xor_sync(0xffffffffu, cP[j], o));
                cN[j] = fminf(cN[j], __shfl_xor_sync(0xffffffffu, cN[j], o));
            }
        }
        int lane = tid & 31;
        if ((lane & 7) == 0) {
#pragma unroll
            for (int i = 0; i < 8; i++) {
                int row = 4 * ty + (i & 3) + (i >> 2) * 32;
                if (row < nrows) {
                    if (rP[i] > 0.f) atomicMax(&g_ap[rowBase + row], __float_as_uint(rP[i]));
                    if (__float_as_uint(rN[i]) != 0x7f800000u) atomicMin(&g_an[rowBase + row], __float_as_uint(rN[i]));
                }
            }
        }
        if (lane < 8) {
#pragma unroll
            for (int j = 0; j < 8; j++) {
                int col = tx + 8 * j;
                if (col < ncols) {
                    if (cP[j] > 0.f) atomicMax(&g_ap[colBase + col], __float_as_uint(cP[j]));
                    if (__float_as_uint(cN[j]) != 0x7f800000u) atomicMin(&g_an[colBase + col], __float_as_uint(cN[j]));
                }
            }
        }
    }
}

__global__ void k_reduce(float* __restrict__ out) {
    __shared__ float s[1024];
    int t = threadIdx.x;
    float acc = 0.f;
    for (int i = t; i < N_SEL; i += 1024) {
        float ap = sqrtf(__uint_as_float(g_ap[i]));
        float an = sqrtf(__uint_as_float(g_an[i]));   // +inf -> loss 0
        acc += fmaxf(ap - an + 0.5f, 0.f);
    }
    s[t] = acc;
    __syncthreads();
    for (int off = 512; off > 0; off >>= 1) {
        if (t < off) s[t] += s[t + off];
        __syncthreads();
    }
    if (t == 0) out[0] = s[0] * (1.0f / (float)BATCH);
}

// ---------------- launch ----------------
extern "C" void kernel_launch(void* const* d_in, const int* in_sizes, int n_in,
                              void* d_out, int out_size) {
    const float* X  = (const float*)d_in[0];
    const int*   T  = (const int*)d_in[1];
    const int*   UU = (const int*)d_in[2];
    float* out = (float*)d_out;
    (void)in_sizes; (void)n_in; (void)out_size;

    const int TB = 256;
    const int gN = (N_TOT + TB - 1) / TB;
    const int gB = NBUCK / TB;
    const int SMEM_MAIN = 2 * KCH * 64 * 8 + 2 * 64 * 4 + 2 * 64 * 4;   // 66560 B
    const int SMEM_RANK = CAP * 8;                                       // 65536 B

    cudaFuncSetAttribute(k_main, cudaFuncAttributeMaxDynamicSharedMemorySize, SMEM_MAIN);
    cudaFuncSetAttribute(k_rank, cudaFuncAttributeMaxDynamicSharedMemorySize, SMEM_RANK);

    k_init<<<gB, TB>>>();
    k_keys<<<gN, TB>>>(UU);
    k_scan<<<64, 1024>>>();
    k_scatter<<<gN, TB>>>();
    k_rank<<<1, 1024, SMEM_RANK>>>();
    k_select<<<(N_SEL + TB - 1) / TB, TB>>>();
    k_gather<<<N_SEL, 64>>>(X, T);
    k_main<<<PGRID, 64, SMEM_MAIN>>>();
    k_reduce<<<1, 1024>>>(out);
}